// round 4
// baseline (speedup 1.0000x reference)
#include <cuda_runtime.h>
#include <cuda_bf16.h>
#include <cstdint>

#define BSZ 4
#define SEQ 2048
#define EMB 1024
#define HD  64

// split-K partial buffers (consumers sum the two halves)
__device__ float g_q [BSZ * SEQ * HD];
__device__ float g_k [BSZ * SEQ * HD];
__device__ float g_v [BSZ * SEQ * HD];
__device__ float g_q2[BSZ * SEQ * HD];
__device__ float g_k2[BSZ * SEQ * HD];
__device__ float g_v2[BSZ * SEQ * HD];
__device__ float g_vmean[BSZ * HD];

typedef unsigned long long u64;

__device__ __forceinline__ u64 splat2(float x) {
    u64 r; asm("mov.b64 %0, {%1, %1};" : "=l"(r) : "f"(x)); return r;
}
__device__ __forceinline__ void fma2(u64& d, u64 a, u64 b) {
    asm("fma.rn.f32x2 %0, %1, %2, %0;" : "+l"(d) : "l"(a), "l"(b));
}
__device__ __forceinline__ void unpack2(u64 v, float& lo, float& hi) {
    asm("mov.b64 {%0, %1}, %2;" : "=f"(lo), "=f"(hi) : "l"(v));
}

// ---------------------------------------------------------------------------
// Kernel 1: QKV projection, split-K=2.
// grid (64, 3, 2): 128-row x 64-head tile, K-half per blockIdx.z.
// 256 threads, frag 4 rows x 8 cols (4 u64). BK=16.
// ---------------------------------------------------------------------------
#define PX 132
#define PW 68

__global__ __launch_bounds__(256) void qkv_kernel(
    const float* __restrict__ x,
    const float* __restrict__ Wq,
    const float* __restrict__ Wk,
    const float* __restrict__ Wv)
{
    const int which = blockIdx.y;
    const int ks    = blockIdx.z;
    const float* W = (which == 0) ? Wq : (which == 1) ? Wk : Wv;
    float* outp = (ks == 0)
        ? ((which == 0) ? g_q  : (which == 1) ? g_k  : g_v)
        : ((which == 0) ? g_q2 : (which == 1) ? g_k2 : g_v2);
    const int row0  = blockIdx.x * 128;
    const int kbase = ks * (EMB / 2);

    __shared__ float sX[16 * PX];
    __shared__ float sW[16 * PW];

    const int tid = threadIdx.x;
    const int tx = tid & 7;        // 8 col-groups of (4 + 4) cols
    const int ty = tid >> 3;       // 32 row-groups of 4

    u64 acc[4][4];
#pragma unroll
    for (int r = 0; r < 4; r++)
#pragma unroll
        for (int c = 0; c < 4; c++) acc[r][c] = 0ULL;

    for (int k0 = kbase; k0 < kbase + EMB / 2; k0 += 16) {
        __syncthreads();
        // stage x: 128 rows x 16 kk (transposed), 2 float4 per thread
#pragma unroll
        for (int u = 0; u < 2; u++) {
            int idx = tid + u * 256;
            int r = idx >> 2, f = (idx & 3) * 4;
            float4 v4 = *reinterpret_cast<const float4*>(
                &x[(size_t)(row0 + r) * EMB + k0 + f]);
            sX[(f + 0) * PX + r] = v4.x;
            sX[(f + 1) * PX + r] = v4.y;
            sX[(f + 2) * PX + r] = v4.z;
            sX[(f + 3) * PX + r] = v4.w;
        }
        // stage W: 64 heads x 16 kk (transposed), 1 float4 per thread
        {
            int h = tid >> 2, f = (tid & 3) * 4;
            float4 v4 = *reinterpret_cast<const float4*>(
                &W[(size_t)h * EMB + k0 + f]);
            sW[(f + 0) * PW + h] = v4.x;
            sW[(f + 1) * PW + h] = v4.y;
            sW[(f + 2) * PW + h] = v4.z;
            sW[(f + 3) * PW + h] = v4.w;
        }
        __syncthreads();

#pragma unroll
        for (int kk = 0; kk < 16; kk++) {
            float4 a4 = *reinterpret_cast<const float4*>(&sX[kk * PX + ty * 4]);
            u64 a2[4];
            a2[0] = splat2(a4.x); a2[1] = splat2(a4.y);
            a2[2] = splat2(a4.z); a2[3] = splat2(a4.w);
            ulonglong2 b0 = *reinterpret_cast<const ulonglong2*>(
                &sW[kk * PW + tx * 4]);
            ulonglong2 b1 = *reinterpret_cast<const ulonglong2*>(
                &sW[kk * PW + 32 + tx * 4]);
#pragma unroll
            for (int r = 0; r < 4; r++) {
                fma2(acc[r][0], a2[r], b0.x);
                fma2(acc[r][1], a2[r], b0.y);
                fma2(acc[r][2], a2[r], b1.x);
                fma2(acc[r][3], a2[r], b1.y);
            }
        }
    }

#pragma unroll
    for (int r = 0; r < 4; r++) {
        const size_t row = row0 + ty * 4 + r;
        float4 o4;
        unpack2(acc[r][0], o4.x, o4.y);
        unpack2(acc[r][1], o4.z, o4.w);
        *reinterpret_cast<float4*>(&outp[row * HD + tx * 4]) = o4;
        unpack2(acc[r][2], o4.x, o4.y);
        unpack2(acc[r][3], o4.z, o4.w);
        *reinterpret_cast<float4*>(&outp[row * HD + 32 + tx * 4]) = o4;
    }
}

// ---------------------------------------------------------------------------
// Kernel 2: per-batch mean of V rows (sums split-K halves).
// ---------------------------------------------------------------------------
__global__ __launch_bounds__(256) void vmean_kernel()
{
    const int b = blockIdx.x;
    const int d = threadIdx.x & 63;
    const int chunk = threadIdx.x >> 6;
    float s = 0.f;
    const int i0 = chunk * (SEQ / 4);
    for (int i = i0; i < i0 + SEQ / 4; i++) {
        size_t off = ((size_t)b * SEQ + i) * HD + d;
        s += g_v[off] + g_v2[off];
    }
    __shared__ float red[256];
    red[threadIdx.x] = s;
    __syncthreads();
    if (chunk == 0)
        g_vmean[b * HD + d] =
            (red[d] + red[64 + d] + red[128 + d] + red[192 + d]) * (1.0f / SEQ);
}

// ---------------------------------------------------------------------------
// Kernel 3: flash attention. 32-row q-tiles x 128-key tiles, 256 threads.
// warp = row-group (4 rows, uniform per warp); lane = 4 keys (S) / 2 dims (PV).
// Heavy-first block order, grid 256.
// ---------------------------------------------------------------------------
#define PQ 36
#define PK 136
#define PVp 68
#define PP 36

#define SM_QT 0
#define SM_KT (SM_QT + 64 * PQ)
#define SM_V  (SM_KT + 64 * PK)
#define SM_PT (SM_V + 128 * PVp)
#define ATTN_SMEM ((SM_PT + 128 * PP) * 4)

__global__ __launch_bounds__(256) void attn_kernel(
    const int* __restrict__ pad, float* __restrict__ out)
{
    const int b  = blockIdx.x & 3;
    const int jq = 63 - (blockIdx.x >> 2);     // heavy q-tiles first
    const int q0 = jq * 32;
    const int tid  = threadIdx.x;
    const int lane = tid & 31;
    const int ty4  = (tid >> 5) * 4;           // row-group base, warp-uniform

    extern __shared__ float smem[];
    float* sQt = smem + SM_QT;   // [d][row]
    float* sKt = smem + SM_KT;   // [d][key]
    float* sV  = smem + SM_V;    // [key][d]
    float* sPt = smem + SM_PT;   // [key][row]
    __shared__ int sPad[128];

    // stage Q transposed (sum split-K halves): 512 float4s, 2 per thread
#pragma unroll
    for (int u = 0; u < 2; u++) {
        int idx = tid + u * 256;
        int r = idx >> 4, f = (idx & 15) * 4;
        size_t off = ((size_t)b * SEQ + q0 + r) * HD + f;
        float4 a = *reinterpret_cast<const float4*>(&g_q[off]);
        float4 c = *reinterpret_cast<const float4*>(&g_q2[off]);
        sQt[(f + 0) * PQ + r] = a.x + c.x;
        sQt[(f + 1) * PQ + r] = a.y + c.y;
        sQt[(f + 2) * PQ + r] = a.z + c.z;
        sQt[(f + 3) * PQ + r] = a.w + c.w;
    }

    float m[4], l[4], o[4][2];
#pragma unroll
    for (int r = 0; r < 4; r++) {
        m[r] = -3.0e38f; l[r] = 0.f; o[r][0] = 0.f; o[r][1] = 0.f;
    }

    const int nkt = q0 / 128 + 1;
    for (int kt = 0; kt < nkt; kt++) {
        const int k0 = kt * 128;
        __syncthreads();

        // stage K transposed: thread = (key, d-half), 8 float4s + sum
        {
            const int key = tid >> 1, dh = (tid & 1) * 32;
            const size_t off = ((size_t)b * SEQ + k0 + key) * HD + dh;
#pragma unroll
            for (int u = 0; u < 8; u++) {
                float4 a = *reinterpret_cast<const float4*>(&g_k[off + u * 4]);
                float4 c = *reinterpret_cast<const float4*>(&g_k2[off + u * 4]);
                sKt[(dh + u * 4 + 0) * PK + key] = a.x + c.x;
                sKt[(dh + u * 4 + 1) * PK + key] = a.y + c.y;
                sKt[(dh + u * 4 + 2) * PK + key] = a.z + c.z;
                sKt[(dh + u * 4 + 3) * PK + key] = a.w + c.w;
            }
        }
        // stage V row-major: 2048 float4s, 8 per thread + sum
#pragma unroll
        for (int u = 0; u < 8; u++) {
            int idx = tid + u * 256;
            int r = idx >> 4, f = (idx & 15) * 4;
            size_t off = ((size_t)b * SEQ + k0 + r) * HD + f;
            float4 a = *reinterpret_cast<const float4*>(&g_v[off]);
            float4 c = *reinterpret_cast<const float4*>(&g_v2[off]);
            float4 s4 = make_float4(a.x + c.x, a.y + c.y, a.z + c.z, a.w + c.w);
            *reinterpret_cast<float4*>(&sV[r * PVp + f]) = s4;
        }
        if (tid < 128) sPad[tid] = pad[b * SEQ + k0 + tid];
        __syncthreads();

        // S = Q K^T: rows ty4..+3, keys lane*4..+3 (2 u64)
        u64 s2[4][2];
#pragma unroll
        for (int r = 0; r < 4; r++) { s2[r][0] = 0ULL; s2[r][1] = 0ULL; }
#pragma unroll 8
        for (int d = 0; d < 64; d++) {
            float4 a4 = *reinterpret_cast<const float4*>(&sQt[d * PQ + ty4]);
            u64 a2[4];
            a2[0] = splat2(a4.x); a2[1] = splat2(a4.y);
            a2[2] = splat2(a4.z); a2[3] = splat2(a4.w);
            ulonglong2 bb = *reinterpret_cast<const ulonglong2*>(
                &sKt[d * PK + lane * 4]);
#pragma unroll
            for (int r = 0; r < 4; r++) {
                fma2(s2[r][0], a2[r], bb.x);
                fma2(s2[r][1], a2[r], bb.y);
            }
        }

        // mask + online softmax (full-warp reductions; rows uniform per warp)
        float p[4][4];
#pragma unroll
        for (int r = 0; r < 4; r++) {
            const int qi = q0 + ty4 + r;
            float sv[4];
            unpack2(s2[r][0], sv[0], sv[1]);
            unpack2(s2[r][1], sv[2], sv[3]);
#pragma unroll
            for (int i = 0; i < 4; i++) {
                const int kj = k0 + lane * 4 + i;
                const bool masked = (kj > qi) || (sPad[lane * 4 + i] == 0);
                sv[i] = (masked ? -1e9f : sv[i]) * 0.125f;
            }
            float tm = fmaxf(fmaxf(sv[0], sv[1]), fmaxf(sv[2], sv[3]));
            tm = fmaxf(tm, __shfl_xor_sync(0xffffffffu, tm, 1));
            tm = fmaxf(tm, __shfl_xor_sync(0xffffffffu, tm, 2));
            tm = fmaxf(tm, __shfl_xor_sync(0xffffffffu, tm, 4));
            tm = fmaxf(tm, __shfl_xor_sync(0xffffffffu, tm, 8));
            tm = fmaxf(tm, __shfl_xor_sync(0xffffffffu, tm, 16));
            const float mnew = fmaxf(m[r], tm);
            const float scale = __expf(m[r] - mnew);
            float tl = 0.f;
#pragma unroll
            for (int i = 0; i < 4; i++) { p[r][i] = __expf(sv[i] - mnew); tl += p[r][i]; }
            tl += __shfl_xor_sync(0xffffffffu, tl, 1);
            tl += __shfl_xor_sync(0xffffffffu, tl, 2);
            tl += __shfl_xor_sync(0xffffffffu, tl, 4);
            tl += __shfl_xor_sync(0xffffffffu, tl, 8);
            tl += __shfl_xor_sync(0xffffffffu, tl, 16);
            l[r] = l[r] * scale + tl;
            m[r] = mnew;
            o[r][0] *= scale; o[r][1] *= scale;
        }
        // store P transposed as float4 over rows (conflict-free)
#pragma unroll
        for (int i = 0; i < 4; i++) {
            float4 p4 = make_float4(p[0][i], p[1][i], p[2][i], p[3][i]);
            *reinterpret_cast<float4*>(&sPt[(lane * 4 + i) * PP + ty4]) = p4;
        }
        __syncthreads();

        // O += P V: dims 2*lane, 2*lane+1 (scalar FFMA)
#pragma unroll 8
        for (int j = 0; j < 128; j++) {
            float4 p4 = *reinterpret_cast<const float4*>(&sPt[j * PP + ty4]);
            float2 v2 = *reinterpret_cast<const float2*>(&sV[j * PVp + lane * 2]);
            o[0][0] = fmaf(p4.x, v2.x, o[0][0]);
            o[0][1] = fmaf(p4.x, v2.y, o[0][1]);
            o[1][0] = fmaf(p4.y, v2.x, o[1][0]);
            o[1][1] = fmaf(p4.y, v2.y, o[1][1]);
            o[2][0] = fmaf(p4.z, v2.x, o[2][0]);
            o[2][1] = fmaf(p4.z, v2.y, o[2][1]);
            o[3][0] = fmaf(p4.w, v2.x, o[3][0]);
            o[3][1] = fmaf(p4.w, v2.y, o[3][1]);
        }
    }

    // epilogue (degenerate all-masked rows -> uniform softmax -> vmean)
#pragma unroll
    for (int r = 0; r < 4; r++) {
        const int row = ty4 + r;
        const bool degen = (m[r] <= -1.0e8f);
        const float invl = 1.0f / l[r];
        float2 res;
        if (degen) {
            res.x = g_vmean[b * HD + lane * 2 + 0];
            res.y = g_vmean[b * HD + lane * 2 + 1];
        } else {
            res.x = o[r][0] * invl;
            res.y = o[r][1] * invl;
        }
        *reinterpret_cast<float2*>(
            &out[((size_t)b * SEQ + q0 + row) * HD + lane * 2]) = res;
    }
}

// ---------------------------------------------------------------------------
extern "C" void kernel_launch(void* const* d_in, const int* in_sizes, int n_in,
                              void* d_out, int out_size)
{
    const float* x   = (const float*)d_in[0];
    const int*   pad = (const int*)  d_in[1];
    const float* Wq  = (const float*)d_in[2];
    const float* Wk  = (const float*)d_in[3];
    const float* Wv  = (const float*)d_in[4];
    float* out = (float*)d_out;

    cudaFuncSetAttribute(attn_kernel,
                         cudaFuncAttributeMaxDynamicSharedMemorySize, ATTN_SMEM);

    qkv_kernel<<<dim3(64, 3, 2), 256>>>(x, Wq, Wk, Wv);
    vmean_kernel<<<BSZ, 256>>>();
    attn_kernel<<<dim3(256), 256, ATTN_SMEM>>>(pad, out);
}

// round 5
// speedup vs baseline: 1.5358x; 1.5358x over previous
#include <cuda_runtime.h>
#include <cuda_bf16.h>
#include <cstdint>

#define BSZ 4
#define SEQ 2048
#define EMB 1024
#define HD  64

// split-K partial buffers (consumers sum the two halves)
__device__ float g_q [BSZ * SEQ * HD];
__device__ float g_k [BSZ * SEQ * HD];
__device__ float g_v [BSZ * SEQ * HD];
__device__ float g_q2[BSZ * SEQ * HD];
__device__ float g_k2[BSZ * SEQ * HD];
__device__ float g_v2[BSZ * SEQ * HD];
__device__ float g_vpart[BSZ * 8 * HD];
__device__ float g_vmean[BSZ * HD];

typedef unsigned long long u64;

__device__ __forceinline__ u64 splat2(float x) {
    u64 r; asm("mov.b64 %0, {%1, %1};" : "=l"(r) : "f"(x)); return r;
}
__device__ __forceinline__ void fma2(u64& d, u64 a, u64 b) {
    asm("fma.rn.f32x2 %0, %1, %2, %0;" : "+l"(d) : "l"(a), "l"(b));
}
__device__ __forceinline__ void mul2(u64& d, u64 s) {
    asm("mul.rn.f32x2 %0, %0, %1;" : "+l"(d) : "l"(s));
}
__device__ __forceinline__ void unpack2(u64 v, float& lo, float& hi) {
    asm("mov.b64 {%0, %1}, %2;" : "=f"(lo), "=f"(hi) : "l"(v));
}

// ---------------------------------------------------------------------------
// Kernel 1: QKV projection, split-K=2.  (UNCHANGED from round 4: 144us)
// ---------------------------------------------------------------------------
#define PX 132
#define PW 68

__global__ __launch_bounds__(256) void qkv_kernel(
    const float* __restrict__ x,
    const float* __restrict__ Wq,
    const float* __restrict__ Wk,
    const float* __restrict__ Wv)
{
    const int which = blockIdx.y;
    const int ks    = blockIdx.z;
    const float* W = (which == 0) ? Wq : (which == 1) ? Wk : Wv;
    float* outp = (ks == 0)
        ? ((which == 0) ? g_q  : (which == 1) ? g_k  : g_v)
        : ((which == 0) ? g_q2 : (which == 1) ? g_k2 : g_v2);
    const int row0  = blockIdx.x * 128;
    const int kbase = ks * (EMB / 2);

    __shared__ float sX[16 * PX];
    __shared__ float sW[16 * PW];

    const int tid = threadIdx.x;
    const int tx = tid & 7;
    const int ty = tid >> 3;

    u64 acc[4][4];
#pragma unroll
    for (int r = 0; r < 4; r++)
#pragma unroll
        for (int c = 0; c < 4; c++) acc[r][c] = 0ULL;

    for (int k0 = kbase; k0 < kbase + EMB / 2; k0 += 16) {
        __syncthreads();
#pragma unroll
        for (int u = 0; u < 2; u++) {
            int idx = tid + u * 256;
            int r = idx >> 2, f = (idx & 3) * 4;
            float4 v4 = *reinterpret_cast<const float4*>(
                &x[(size_t)(row0 + r) * EMB + k0 + f]);
            sX[(f + 0) * PX + r] = v4.x;
            sX[(f + 1) * PX + r] = v4.y;
            sX[(f + 2) * PX + r] = v4.z;
            sX[(f + 3) * PX + r] = v4.w;
        }
        {
            int h = tid >> 2, f = (tid & 3) * 4;
            float4 v4 = *reinterpret_cast<const float4*>(
                &W[(size_t)h * EMB + k0 + f]);
            sW[(f + 0) * PW + h] = v4.x;
            sW[(f + 1) * PW + h] = v4.y;
            sW[(f + 2) * PW + h] = v4.z;
            sW[(f + 3) * PW + h] = v4.w;
        }
        __syncthreads();

#pragma unroll
        for (int kk = 0; kk < 16; kk++) {
            float4 a4 = *reinterpret_cast<const float4*>(&sX[kk * PX + ty * 4]);
            u64 a2[4];
            a2[0] = splat2(a4.x); a2[1] = splat2(a4.y);
            a2[2] = splat2(a4.z); a2[3] = splat2(a4.w);
            ulonglong2 b0 = *reinterpret_cast<const ulonglong2*>(
                &sW[kk * PW + tx * 4]);
            ulonglong2 b1 = *reinterpret_cast<const ulonglong2*>(
                &sW[kk * PW + 32 + tx * 4]);
#pragma unroll
            for (int r = 0; r < 4; r++) {
                fma2(acc[r][0], a2[r], b0.x);
                fma2(acc[r][1], a2[r], b0.y);
                fma2(acc[r][2], a2[r], b1.x);
                fma2(acc[r][3], a2[r], b1.y);
            }
        }
    }

#pragma unroll
    for (int r = 0; r < 4; r++) {
        const size_t row = row0 + ty * 4 + r;
        float4 o4;
        unpack2(acc[r][0], o4.x, o4.y);
        unpack2(acc[r][1], o4.z, o4.w);
        *reinterpret_cast<float4*>(&outp[row * HD + tx * 4]) = o4;
        unpack2(acc[r][2], o4.x, o4.y);
        unpack2(acc[r][3], o4.z, o4.w);
        *reinterpret_cast<float4*>(&outp[row * HD + 32 + tx * 4]) = o4;
    }
}

// ---------------------------------------------------------------------------
// Kernel 2a/2b: per-batch mean of V rows, parallel partials then reduce.
// ---------------------------------------------------------------------------
__global__ __launch_bounds__(256) void vmean1_kernel()
{
    const int b = blockIdx.x;
    const int c = blockIdx.y;               // chunk of 256 rows
    const int d = threadIdx.x & 63;
    const int sub = threadIdx.x >> 6;       // 0..3 (64 rows each)
    float s = 0.f;
    const int i0 = c * 256 + sub * 64;
#pragma unroll 4
    for (int i = i0; i < i0 + 64; i++) {
        size_t off = ((size_t)b * SEQ + i) * HD + d;
        s += g_v[off] + g_v2[off];
    }
    __shared__ float red[256];
    red[threadIdx.x] = s;
    __syncthreads();
    if (sub == 0)
        g_vpart[(b * 8 + c) * HD + d] =
            red[d] + red[64 + d] + red[128 + d] + red[192 + d];
}

__global__ __launch_bounds__(64) void vmean2_kernel()
{
    const int b = blockIdx.x;
    const int d = threadIdx.x;
    float s = 0.f;
#pragma unroll
    for (int c = 0; c < 8; c++) s += g_vpart[(b * 8 + c) * HD + d];
    g_vmean[b * HD + d] = s * (1.0f / SEQ);
}

// ---------------------------------------------------------------------------
// Kernel 3: flash attention, fma2 throughout.
// 32-row q-tile x 128-key tiles, 256 threads (8 warps x 4 rows), grid 256.
// Block->q-tile mapping exploits bid%148 SM pairing: bids 108..147 carry the
// 40 heaviest tiles (jq 54..63) alone; pairs (j, j+148) carry (a, 53-a).
// ---------------------------------------------------------------------------
#define PQ 36
#define PK 132
#define PVv 68
#define PP 44

#define SM_QT 0
#define SM_KT (SM_QT + 64 * PQ)
#define SM_V  (SM_KT + 64 * PK)
#define SM_PT (SM_V + 128 * PVv)
#define ATTN_SMEM ((SM_PT + 128 * PP) * 4)

__global__ __launch_bounds__(256, 2) void attn_kernel(
    const int* __restrict__ pad, float* __restrict__ out)
{
    // balanced bid -> (batch, q-tile) mapping
    int bid = blockIdx.x, b, jq;
    if (bid < 108)      { jq = bid >> 2;              b = bid & 3; }
    else if (bid < 148) { jq = 54 + ((bid - 108) >> 2); b = (bid - 108) & 3; }
    else                { jq = 53 - ((bid - 148) >> 2); b = (bid - 148) & 3; }
    const int q0 = jq * 32;
    const int tid  = threadIdx.x;
    const int lane = tid & 31;
    const int ty4  = (tid >> 5) * 4;       // warp-uniform row base

    extern __shared__ float smem[];
    float* sQt = smem + SM_QT;   // [d][row]
    float* sKt = smem + SM_KT;   // [d][key]
    float* sV  = smem + SM_V;    // [key][d]
    float* sPt = smem + SM_PT;   // [key][row]
    __shared__ int sPad[128];

    // stage Q transposed (sum split-K halves)
#pragma unroll
    for (int u = 0; u < 2; u++) {
        int idx = tid + u * 256;
        int r = idx >> 4, f = (idx & 15) * 4;
        size_t off = ((size_t)b * SEQ + q0 + r) * HD + f;
        float4 a = *reinterpret_cast<const float4*>(&g_q[off]);
        float4 c = *reinterpret_cast<const float4*>(&g_q2[off]);
        sQt[(f + 0) * PQ + r] = a.x + c.x;
        sQt[(f + 1) * PQ + r] = a.y + c.y;
        sQt[(f + 2) * PQ + r] = a.z + c.z;
        sQt[(f + 3) * PQ + r] = a.w + c.w;
    }

    float m[4], l[4];
    u64 o2[4];
#pragma unroll
    for (int r = 0; r < 4; r++) { m[r] = -3.0e38f; l[r] = 0.f; o2[r] = 0ULL; }

    const int nkt = q0 / 128 + 1;
    for (int kt = 0; kt < nkt; kt++) {
        const int k0 = kt * 128;
        __syncthreads();

        // stage K transposed: thread = (key, d-half)
        {
            const int key = tid >> 1, dh = (tid & 1) * 32;
            const size_t off = ((size_t)b * SEQ + k0 + key) * HD + dh;
#pragma unroll
            for (int u = 0; u < 8; u++) {
                float4 a = *reinterpret_cast<const float4*>(&g_k[off + u * 4]);
                float4 c = *reinterpret_cast<const float4*>(&g_k2[off + u * 4]);
                sKt[(dh + u * 4 + 0) * PK + key] = a.x + c.x;
                sKt[(dh + u * 4 + 1) * PK + key] = a.y + c.y;
                sKt[(dh + u * 4 + 2) * PK + key] = a.z + c.z;
                sKt[(dh + u * 4 + 3) * PK + key] = a.w + c.w;
            }
        }
        // stage V row-major
#pragma unroll
        for (int u = 0; u < 8; u++) {
            int idx = tid + u * 256;
            int r = idx >> 4, f = (idx & 15) * 4;
            size_t off = ((size_t)b * SEQ + k0 + r) * HD + f;
            float4 a = *reinterpret_cast<const float4*>(&g_v[off]);
            float4 c = *reinterpret_cast<const float4*>(&g_v2[off]);
            float4 s4 = make_float4(a.x + c.x, a.y + c.y, a.z + c.z, a.w + c.w);
            *reinterpret_cast<float4*>(&sV[r * PVv + f]) = s4;
        }
        if (tid < 128) sPad[tid] = pad[b * SEQ + k0 + tid];
        __syncthreads();

        // S = Q K^T: rows ty4..+3, keys lane*4..+3
        u64 s2[4][2];
#pragma unroll
        for (int r = 0; r < 4; r++) { s2[r][0] = 0ULL; s2[r][1] = 0ULL; }
#pragma unroll 8
        for (int d = 0; d < 64; d++) {
            float4 a4 = *reinterpret_cast<const float4*>(&sQt[d * PQ + ty4]);
            u64 a2[4];
            a2[0] = splat2(a4.x); a2[1] = splat2(a4.y);
            a2[2] = splat2(a4.z); a2[3] = splat2(a4.w);
            ulonglong2 bb = *reinterpret_cast<const ulonglong2*>(
                &sKt[d * PK + lane * 4]);
#pragma unroll
            for (int r = 0; r < 4; r++) {
                fma2(s2[r][0], a2[r], bb.x);
                fma2(s2[r][1], a2[r], bb.y);
            }
        }

        // mask + online softmax
        float p[4][4];
#pragma unroll
        for (int r = 0; r < 4; r++) {
            const int qi = q0 + ty4 + r;
            float sv[4];
            unpack2(s2[r][0], sv[0], sv[1]);
            unpack2(s2[r][1], sv[2], sv[3]);
#pragma unroll
            for (int i = 0; i < 4; i++) {
                const int kj = k0 + lane * 4 + i;
                const bool masked = (kj > qi) || (sPad[lane * 4 + i] == 0);
                sv[i] = (masked ? -1e9f : sv[i]) * 0.125f;
            }
            float tm = fmaxf(fmaxf(sv[0], sv[1]), fmaxf(sv[2], sv[3]));
            tm = fmaxf(tm, __shfl_xor_sync(0xffffffffu, tm, 1));
            tm = fmaxf(tm, __shfl_xor_sync(0xffffffffu, tm, 2));
            tm = fmaxf(tm, __shfl_xor_sync(0xffffffffu, tm, 4));
            tm = fmaxf(tm, __shfl_xor_sync(0xffffffffu, tm, 8));
            tm = fmaxf(tm, __shfl_xor_sync(0xffffffffu, tm, 16));
            const float mnew = fmaxf(m[r], tm);
            const float scale = __expf(m[r] - mnew);
            float tl = 0.f;
#pragma unroll
            for (int i = 0; i < 4; i++) { p[r][i] = __expf(sv[i] - mnew); tl += p[r][i]; }
            tl += __shfl_xor_sync(0xffffffffu, tl, 1);
            tl += __shfl_xor_sync(0xffffffffu, tl, 2);
            tl += __shfl_xor_sync(0xffffffffu, tl, 4);
            tl += __shfl_xor_sync(0xffffffffu, tl, 8);
            tl += __shfl_xor_sync(0xffffffffu, tl, 16);
            l[r] = l[r] * scale + tl;
            m[r] = mnew;
            mul2(o2[r], splat2(scale));
        }
        // store P transposed (float4 over rows; PP=44 -> 4-way max conflict)
#pragma unroll
        for (int i = 0; i < 4; i++) {
            float4 p4 = make_float4(p[0][i], p[1][i], p[2][i], p[3][i]);
            *reinterpret_cast<float4*>(&sPt[(lane * 4 + i) * PP + ty4]) = p4;
        }
        __syncthreads();

        // O += P V: lane = dim pair (2*lane, 2*lane+1), fma2
#pragma unroll 8
        for (int j = 0; j < 128; j++) {
            float4 p4 = *reinterpret_cast<const float4*>(&sPt[j * PP + ty4]);
            u64 v2 = *reinterpret_cast<const u64*>(&sV[j * PVv + lane * 2]);
            fma2(o2[0], splat2(p4.x), v2);
            fma2(o2[1], splat2(p4.y), v2);
            fma2(o2[2], splat2(p4.z), v2);
            fma2(o2[3], splat2(p4.w), v2);
        }
    }

    // epilogue (all-masked rows -> uniform softmax over all keys -> vmean)
#pragma unroll
    for (int r = 0; r < 4; r++) {
        const int row = ty4 + r;
        const bool degen = (m[r] <= -1.0e8f);
        const float invl = 1.0f / l[r];
        float2 res;
        unpack2(o2[r], res.x, res.y);
        if (degen) {
            res.x = g_vmean[b * HD + lane * 2 + 0];
            res.y = g_vmean[b * HD + lane * 2 + 1];
        } else {
            res.x *= invl; res.y *= invl;
        }
        *reinterpret_cast<float2*>(
            &out[((size_t)b * SEQ + q0 + row) * HD + lane * 2]) = res;
    }
}

// ---------------------------------------------------------------------------
extern "C" void kernel_launch(void* const* d_in, const int* in_sizes, int n_in,
                              void* d_out, int out_size)
{
    const float* x   = (const float*)d_in[0];
    const int*   pad = (const int*)  d_in[1];
    const float* Wq  = (const float*)d_in[2];
    const float* Wk  = (const float*)d_in[3];
    const float* Wv  = (const float*)d_in[4];
    float* out = (float*)d_out;

    cudaFuncSetAttribute(attn_kernel,
                         cudaFuncAttributeMaxDynamicSharedMemorySize, ATTN_SMEM);

    qkv_kernel<<<dim3(64, 3, 2), 256>>>(x, Wq, Wk, Wv);
    vmean1_kernel<<<dim3(BSZ, 8), 256>>>();
    vmean2_kernel<<<BSZ, 64>>>();
    attn_kernel<<<dim3(256), 256, ATTN_SMEM>>>(pad, out);
}

// round 6
// speedup vs baseline: 2.2981x; 1.4963x over previous
#include <cuda_runtime.h>
#include <cuda_bf16.h>
#include <cstdint>

#define BSZ 4
#define SEQ 2048
#define EMB 1024
#define HD  64

// qkv split-K=4 partials
__device__ float g_q [BSZ * SEQ * HD];
__device__ float g_q2[BSZ * SEQ * HD];
__device__ float g_q3[BSZ * SEQ * HD];
__device__ float g_q4[BSZ * SEQ * HD];
__device__ float g_k [BSZ * SEQ * HD];
__device__ float g_k2[BSZ * SEQ * HD];
__device__ float g_k3[BSZ * SEQ * HD];
__device__ float g_k4[BSZ * SEQ * HD];
__device__ float g_v [BSZ * SEQ * HD];
__device__ float g_v2[BSZ * SEQ * HD];
__device__ float g_v3[BSZ * SEQ * HD];
__device__ float g_v4[BSZ * SEQ * HD];
// summed
__device__ float g_qs[BSZ * SEQ * HD];
__device__ float g_ks[BSZ * SEQ * HD];
__device__ float g_vs[BSZ * SEQ * HD];
// vmean
__device__ float g_vpart[BSZ * 8 * HD];
__device__ float g_vmean[BSZ * HD];
// attention split-key partials: 320 jobs (80 per batch)
#define NJOBS 320
__device__ float g_pm[NJOBS * 64];
__device__ float g_pl[NJOBS * 64];
__device__ float g_po[NJOBS * 64 * 64];

typedef unsigned long long u64;

__device__ __forceinline__ u64 splat2(float x) {
    u64 r; asm("mov.b64 %0, {%1, %1};" : "=l"(r) : "f"(x)); return r;
}
__device__ __forceinline__ u64 pack2(float lo, float hi) {
    u64 r; asm("mov.b64 %0, {%1, %2};" : "=l"(r) : "f"(lo), "f"(hi)); return r;
}
__device__ __forceinline__ void fma2(u64& d, u64 a, u64 b) {
    asm("fma.rn.f32x2 %0, %1, %2, %0;" : "+l"(d) : "l"(a), "l"(b));
}
__device__ __forceinline__ void mul2(u64& d, u64 s) {
    asm("mul.rn.f32x2 %0, %0, %1;" : "+l"(d) : "l"(s));
}
__device__ __forceinline__ void unpack2(u64 v, float& lo, float& hi) {
    asm("mov.b64 {%0, %1}, %2;" : "=f"(lo), "=f"(hi) : "l"(v));
}

// ---------------------------------------------------------------------------
// Kernel 1: QKV projection, split-K=4.  grid (64, 3, 4), 256 threads.
// ---------------------------------------------------------------------------
#define PX 132
#define PW 68

__global__ __launch_bounds__(256) void qkv_kernel(
    const float* __restrict__ x,
    const float* __restrict__ Wq,
    const float* __restrict__ Wk,
    const float* __restrict__ Wv)
{
    const int which = blockIdx.y;
    const int ks    = blockIdx.z;
    const float* W = (which == 0) ? Wq : (which == 1) ? Wk : Wv;
    float* outp;
    if (which == 0)      outp = (ks == 0) ? g_q : (ks == 1) ? g_q2 : (ks == 2) ? g_q3 : g_q4;
    else if (which == 1) outp = (ks == 0) ? g_k : (ks == 1) ? g_k2 : (ks == 2) ? g_k3 : g_k4;
    else                 outp = (ks == 0) ? g_v : (ks == 1) ? g_v2 : (ks == 2) ? g_v3 : g_v4;
    const int row0  = blockIdx.x * 128;
    const int kbase = ks * (EMB / 4);

    __shared__ float sX[16 * PX];
    __shared__ float sW[16 * PW];

    const int tid = threadIdx.x;
    const int tx = tid & 7;
    const int ty = tid >> 3;

    u64 acc[4][4];
#pragma unroll
    for (int r = 0; r < 4; r++)
#pragma unroll
        for (int c = 0; c < 4; c++) acc[r][c] = 0ULL;

    for (int k0 = kbase; k0 < kbase + EMB / 4; k0 += 16) {
        __syncthreads();
#pragma unroll
        for (int u = 0; u < 2; u++) {
            int idx = tid + u * 256;
            int r = idx >> 2, f = (idx & 3) * 4;
            float4 v4 = *reinterpret_cast<const float4*>(
                &x[(size_t)(row0 + r) * EMB + k0 + f]);
            sX[(f + 0) * PX + r] = v4.x;
            sX[(f + 1) * PX + r] = v4.y;
            sX[(f + 2) * PX + r] = v4.z;
            sX[(f + 3) * PX + r] = v4.w;
        }
        {
            int h = tid >> 2, f = (tid & 3) * 4;
            float4 v4 = *reinterpret_cast<const float4*>(
                &W[(size_t)h * EMB + k0 + f]);
            sW[(f + 0) * PW + h] = v4.x;
            sW[(f + 1) * PW + h] = v4.y;
            sW[(f + 2) * PW + h] = v4.z;
            sW[(f + 3) * PW + h] = v4.w;
        }
        __syncthreads();

#pragma unroll
        for (int kk = 0; kk < 16; kk++) {
            float4 a4 = *reinterpret_cast<const float4*>(&sX[kk * PX + ty * 4]);
            u64 a2[4];
            a2[0] = splat2(a4.x); a2[1] = splat2(a4.y);
            a2[2] = splat2(a4.z); a2[3] = splat2(a4.w);
            ulonglong2 b0 = *reinterpret_cast<const ulonglong2*>(
                &sW[kk * PW + tx * 4]);
            ulonglong2 b1 = *reinterpret_cast<const ulonglong2*>(
                &sW[kk * PW + 32 + tx * 4]);
#pragma unroll
            for (int r = 0; r < 4; r++) {
                fma2(acc[r][0], a2[r], b0.x);
                fma2(acc[r][1], a2[r], b0.y);
                fma2(acc[r][2], a2[r], b1.x);
                fma2(acc[r][3], a2[r], b1.y);
            }
        }
    }

#pragma unroll
    for (int r = 0; r < 4; r++) {
        const size_t row = row0 + ty * 4 + r;
        float4 o4;
        unpack2(acc[r][0], o4.x, o4.y);
        unpack2(acc[r][1], o4.z, o4.w);
        *reinterpret_cast<float4*>(&outp[row * HD + tx * 4]) = o4;
        unpack2(acc[r][2], o4.x, o4.y);
        unpack2(acc[r][3], o4.z, o4.w);
        *reinterpret_cast<float4*>(&outp[row * HD + 32 + tx * 4]) = o4;
    }
}

// ---------------------------------------------------------------------------
// Kernel 2: sum the 4 split-K partials into g_qs/g_ks/g_vs.
// grid (512, 3), 256 threads; one float4 per thread.
// ---------------------------------------------------------------------------
__global__ __launch_bounds__(256) void sumqkv_kernel()
{
    const int i = blockIdx.x * 256 + threadIdx.x;   // float4 index
    const int w = blockIdx.y;
    const float4* a; const float4* b; const float4* c; const float4* d;
    float4* o;
    if (w == 0) { a=(const float4*)g_q; b=(const float4*)g_q2; c=(const float4*)g_q3; d=(const float4*)g_q4; o=(float4*)g_qs; }
    else if (w == 1) { a=(const float4*)g_k; b=(const float4*)g_k2; c=(const float4*)g_k3; d=(const float4*)g_k4; o=(float4*)g_ks; }
    else { a=(const float4*)g_v; b=(const float4*)g_v2; c=(const float4*)g_v3; d=(const float4*)g_v4; o=(float4*)g_vs; }
    float4 ra = a[i], rb = b[i], rc = c[i], rd = d[i];
    o[i] = make_float4(ra.x+rb.x+rc.x+rd.x, ra.y+rb.y+rc.y+rd.y,
                       ra.z+rb.z+rc.z+rd.z, ra.w+rb.w+rc.w+rd.w);
}

// ---------------------------------------------------------------------------
// Kernel 3a/3b: per-batch mean of V rows.
// ---------------------------------------------------------------------------
__global__ __launch_bounds__(256) void vmean1_kernel()
{
    const int b = blockIdx.x;
    const int c = blockIdx.y;
    const int d = threadIdx.x & 63;
    const int sub = threadIdx.x >> 6;
    float s = 0.f;
    const int i0 = c * 256 + sub * 64;
#pragma unroll 4
    for (int i = i0; i < i0 + 64; i++)
        s += g_vs[((size_t)b * SEQ + i) * HD + d];
    __shared__ float red[256];
    red[threadIdx.x] = s;
    __syncthreads();
    if (sub == 0)
        g_vpart[(b * 8 + c) * HD + d] =
            red[d] + red[64 + d] + red[128 + d] + red[192 + d];
}

__global__ __launch_bounds__(64) void vmean2_kernel()
{
    const int b = blockIdx.x;
    const int d = threadIdx.x;
    float s = 0.f;
#pragma unroll
    for (int c = 0; c < 8; c++) s += g_vpart[(b * 8 + c) * HD + d];
    g_vmean[b * HD + d] = s * (1.0f / SEQ);
}

// ---------------------------------------------------------------------------
// Kernel 4: attention partial. Job = (batch, 64-row q-tile, <=512-key chunk).
// 80 jobs/batch, 320 total. 256 threads = 8 warps x 8 rows.
// Writes unnormalized (m, l, o) partials.
// ---------------------------------------------------------------------------
#define PQ2 68
#define PK2 132
#define PV2 68
#define PP2 68

#define A_QT 0
#define A_KT (A_QT + 64 * PQ2)
#define A_V  (A_KT + 64 * PK2)
#define A_PT (A_V + 128 * PV2)
#define ATTN_SMEM ((A_PT + 128 * PP2) * 4)

__global__ __launch_bounds__(256) void attn_partial_kernel(
    const int* __restrict__ pad)
{
    // decode job
    const int bid = blockIdx.x;
    const int b = bid / 80;
    const int rem = bid - b * 80;
    int jq, ch;
    if (rem < 8)       { jq = rem;                   ch = 0; }
    else if (rem < 24) { jq = 8 + ((rem - 8) >> 1);  ch = (rem - 8) & 1; }
    else if (rem < 48) { jq = 16 + (rem - 24) / 3;   ch = (rem - 24) % 3; }
    else               { jq = 24 + ((rem - 48) >> 2); ch = (rem - 48) & 3; }
    const int q0 = jq * 64;
    const int kstart = ch * 512;
    const int kmax = q0 + 64;
    const int kend = (kstart + 512 < kmax) ? kstart + 512 : kmax;
    const int nkt = (kend - kstart + 127) >> 7;

    const int tid  = threadIdx.x;
    const int lane = tid & 31;
    const int ty8  = (tid >> 5) * 8;       // warp row base (8 rows)

    extern __shared__ float smem[];
    float* sQt = smem + A_QT;    // [d][row]   pitch 68
    float* sKt = smem + A_KT;    // [d][key]   pitch 132
    float* sV  = smem + A_V;     // [key][d]   pitch 68
    float* sPt = smem + A_PT;    // [key][row] pitch 68
    __shared__ int sPad[128];

    // stage Q transposed: 64 rows x 64 dims = 1024 float4s, 4/thread
#pragma unroll
    for (int u = 0; u < 4; u++) {
        int idx = tid + u * 256;
        int r = idx >> 4, f = (idx & 15) * 4;
        float4 v4 = *reinterpret_cast<const float4*>(
            &g_qs[((size_t)b * SEQ + q0 + r) * HD + f]);
        sQt[(f + 0) * PQ2 + r] = v4.x;
        sQt[(f + 1) * PQ2 + r] = v4.y;
        sQt[(f + 2) * PQ2 + r] = v4.z;
        sQt[(f + 3) * PQ2 + r] = v4.w;
    }

    float m[8], l[8];
    u64 o2[4][2];                 // [row-pair][dim], rows (ty8+2p, ty8+2p+1)
#pragma unroll
    for (int r = 0; r < 8; r++) { m[r] = -3.0e38f; l[r] = 0.f; }
#pragma unroll
    for (int p = 0; p < 4; p++) { o2[p][0] = 0ULL; o2[p][1] = 0ULL; }

    for (int kt = 0; kt < nkt; kt++) {
        const int k0 = kstart + kt * 128;
        __syncthreads();

        // stage K transposed: thread = (key, d-half)
        {
            const int key = tid >> 1, dh = (tid & 1) * 32;
            const size_t off = ((size_t)b * SEQ + k0 + key) * HD + dh;
#pragma unroll
            for (int u = 0; u < 8; u++) {
                float4 a = *reinterpret_cast<const float4*>(&g_ks[off + u * 4]);
                sKt[(dh + u * 4 + 0) * PK2 + key] = a.x;
                sKt[(dh + u * 4 + 1) * PK2 + key] = a.y;
                sKt[(dh + u * 4 + 2) * PK2 + key] = a.z;
                sKt[(dh + u * 4 + 3) * PK2 + key] = a.w;
            }
        }
        // stage V row-major: 2048 float4s, 8/thread
#pragma unroll
        for (int u = 0; u < 8; u++) {
            int idx = tid + u * 256;
            int r = idx >> 4, f = (idx & 15) * 4;
            float4 a = *reinterpret_cast<const float4*>(
                &g_vs[((size_t)b * SEQ + k0 + r) * HD + f]);
            *reinterpret_cast<float4*>(&sV[r * PV2 + f]) = a;
        }
        if (tid < 128) sPad[tid] = pad[b * SEQ + k0 + tid];
        __syncthreads();

        // S = Q K^T: 8 rows (as 4 row-pairs) x 4 keys per lane
        u64 s2[4][4];
#pragma unroll
        for (int p = 0; p < 4; p++)
#pragma unroll
            for (int i = 0; i < 4; i++) s2[p][i] = 0ULL;
#pragma unroll 8
        for (int d = 0; d < 64; d++) {
            ulonglong2 qA = *reinterpret_cast<const ulonglong2*>(&sQt[d * PQ2 + ty8]);
            ulonglong2 qB = *reinterpret_cast<const ulonglong2*>(&sQt[d * PQ2 + ty8 + 4]);
            float4 kv = *reinterpret_cast<const float4*>(&sKt[d * PK2 + lane * 4]);
            u64 k0s = splat2(kv.x), k1s = splat2(kv.y);
            u64 k2s = splat2(kv.z), k3s = splat2(kv.w);
            fma2(s2[0][0], qA.x, k0s); fma2(s2[0][1], qA.x, k1s);
            fma2(s2[0][2], qA.x, k2s); fma2(s2[0][3], qA.x, k3s);
            fma2(s2[1][0], qA.y, k0s); fma2(s2[1][1], qA.y, k1s);
            fma2(s2[1][2], qA.y, k2s); fma2(s2[1][3], qA.y, k3s);
            fma2(s2[2][0], qB.x, k0s); fma2(s2[2][1], qB.x, k1s);
            fma2(s2[2][2], qB.x, k2s); fma2(s2[2][3], qB.x, k3s);
            fma2(s2[3][0], qB.y, k0s); fma2(s2[3][1], qB.y, k1s);
            fma2(s2[3][2], qB.y, k2s); fma2(s2[3][3], qB.y, k3s);
        }

        // unpack into per-row score rows
        float sv[8][4];
#pragma unroll
        for (int p = 0; p < 4; p++)
#pragma unroll
            for (int i = 0; i < 4; i++)
                unpack2(s2[p][i], sv[2 * p][i], sv[2 * p + 1][i]);

        // mask + online softmax per row
        float p8[8][4], scl[8];
#pragma unroll
        for (int r = 0; r < 8; r++) {
            const int qi = q0 + ty8 + r;
#pragma unroll
            for (int i = 0; i < 4; i++) {
                const int kj = k0 + lane * 4 + i;
                const bool masked = (kj > qi) || (sPad[lane * 4 + i] == 0);
                sv[r][i] = (masked ? -1e9f : sv[r][i]) * 0.125f;
            }
            float tm = fmaxf(fmaxf(sv[r][0], sv[r][1]), fmaxf(sv[r][2], sv[r][3]));
            tm = fmaxf(tm, __shfl_xor_sync(0xffffffffu, tm, 1));
            tm = fmaxf(tm, __shfl_xor_sync(0xffffffffu, tm, 2));
            tm = fmaxf(tm, __shfl_xor_sync(0xffffffffu, tm, 4));
            tm = fmaxf(tm, __shfl_xor_sync(0xffffffffu, tm, 8));
            tm = fmaxf(tm, __shfl_xor_sync(0xffffffffu, tm, 16));
            const float mnew = fmaxf(m[r], tm);
            scl[r] = __expf(m[r] - mnew);
            float tl = 0.f;
#pragma unroll
            for (int i = 0; i < 4; i++) { p8[r][i] = __expf(sv[r][i] - mnew); tl += p8[r][i]; }
            tl += __shfl_xor_sync(0xffffffffu, tl, 1);
            tl += __shfl_xor_sync(0xffffffffu, tl, 2);
            tl += __shfl_xor_sync(0xffffffffu, tl, 4);
            tl += __shfl_xor_sync(0xffffffffu, tl, 8);
            tl += __shfl_xor_sync(0xffffffffu, tl, 16);
            l[r] = l[r] * scl[r] + tl;
            m[r] = mnew;
        }
        // rescale O (per row-pair packed scales)
#pragma unroll
        for (int p = 0; p < 4; p++) {
            u64 sp = pack2(scl[2 * p], scl[2 * p + 1]);
            mul2(o2[p][0], sp);
            mul2(o2[p][1], sp);
        }
        // store P transposed: per key, float4 over 4 rows (x2)
#pragma unroll
        for (int i = 0; i < 4; i++) {
            const int key = lane * 4 + i;
            *reinterpret_cast<float4*>(&sPt[key * PP2 + ty8]) =
                make_float4(p8[0][i], p8[1][i], p8[2][i], p8[3][i]);
            *reinterpret_cast<float4*>(&sPt[key * PP2 + ty8 + 4]) =
                make_float4(p8[4][i], p8[5][i], p8[6][i], p8[7][i]);
        }
        __syncthreads();

        // O += P V: lane owns dims (2lane, 2lane+1); rows paired
#pragma unroll 8
        for (int j = 0; j < 128; j++) {
            ulonglong2 pA = *reinterpret_cast<const ulonglong2*>(&sPt[j * PP2 + ty8]);
            ulonglong2 pB = *reinterpret_cast<const ulonglong2*>(&sPt[j * PP2 + ty8 + 4]);
            float2 v2 = *reinterpret_cast<const float2*>(&sV[j * PV2 + lane * 2]);
            u64 v0 = splat2(v2.x), v1 = splat2(v2.y);
            fma2(o2[0][0], pA.x, v0); fma2(o2[0][1], pA.x, v1);
            fma2(o2[1][0], pA.y, v0); fma2(o2[1][1], pA.y, v1);
            fma2(o2[2][0], pB.x, v0); fma2(o2[2][1], pB.x, v1);
            fma2(o2[3][0], pB.y, v0); fma2(o2[3][1], pB.y, v1);
        }
    }

    // write partials: m, l (lane 0 per warp), o (unnormalized)
    if (lane == 0) {
#pragma unroll
        for (int r = 0; r < 8; r++) {
            g_pm[bid * 64 + ty8 + r] = m[r];
            g_pl[bid * 64 + ty8 + r] = l[r];
        }
    }
#pragma unroll
    for (int p = 0; p < 4; p++) {
        float aLo, aHi, bLo, bHi;
        unpack2(o2[p][0], aLo, aHi);   // dim0: rows 2p, 2p+1
        unpack2(o2[p][1], bLo, bHi);   // dim1: rows 2p, 2p+1
        *reinterpret_cast<float2*>(
            &g_po[(size_t)bid * 4096 + (ty8 + 2 * p) * 64 + lane * 2]) =
            make_float2(aLo, bLo);
        *reinterpret_cast<float2*>(
            &g_po[(size_t)bid * 4096 + (ty8 + 2 * p + 1) * 64 + lane * 2]) =
            make_float2(aHi, bHi);
    }
}

// ---------------------------------------------------------------------------
// Kernel 5: merge partials.  grid 128 = (b, jq); 256 threads.
// ---------------------------------------------------------------------------
__global__ __launch_bounds__(256) void attn_merge_kernel(float* __restrict__ out)
{
    const int b  = blockIdx.x >> 5;
    const int jq = blockIdx.x & 31;
    int off;
    if (jq < 8)       off = jq;
    else if (jq < 16) off = 8 + 2 * (jq - 8);
    else if (jq < 24) off = 24 + 3 * (jq - 16);
    else              off = 48 + 4 * (jq - 24);
    const int nch = (jq >> 3) + 1;
    const int jbase = b * 80 + off;
    const int q0 = jq * 64;

    const int d  = threadIdx.x & 63;
    const int r0 = threadIdx.x >> 6;     // rows r0, r0+4, ..., r0+60

    for (int rr = 0; rr < 16; rr++) {
        const int row = r0 + rr * 4;
        float M = -3.0e38f;
        float mi[5], li[5];
#pragma unroll 5
        for (int i = 0; i < 5; i++) {
            if (i < nch) {
                mi[i] = g_pm[(jbase + i) * 64 + row];
                li[i] = g_pl[(jbase + i) * 64 + row];
                M = fmaxf(M, mi[i]);
            }
        }
        float L = 0.f, O = 0.f;
#pragma unroll 5
        for (int i = 0; i < 5; i++) {
            if (i < nch) {
                float w = __expf(mi[i] - M);
                L += li[i] * w;
                O += g_po[(size_t)(jbase + i) * 4096 + row * 64 + d] * w;
            }
        }
        float res = (M <= -1.0e8f) ? g_vmean[b * HD + d] : O / L;
        out[((size_t)b * SEQ + q0 + row) * HD + d] = res;
    }
}

// ---------------------------------------------------------------------------
extern "C" void kernel_launch(void* const* d_in, const int* in_sizes, int n_in,
                              void* d_out, int out_size)
{
    const float* x   = (const float*)d_in[0];
    const int*   pad = (const int*)  d_in[1];
    const float* Wq  = (const float*)d_in[2];
    const float* Wk  = (const float*)d_in[3];
    const float* Wv  = (const float*)d_in[4];
    float* out = (float*)d_out;

    cudaFuncSetAttribute(attn_partial_kernel,
                         cudaFuncAttributeMaxDynamicSharedMemorySize, ATTN_SMEM);

    qkv_kernel<<<dim3(64, 3, 4), 256>>>(x, Wq, Wk, Wv);
    sumqkv_kernel<<<dim3(512, 3), 256>>>();
    vmean1_kernel<<<dim3(BSZ, 8), 256>>>();
    vmean2_kernel<<<BSZ, 64>>>();
    attn_partial_kernel<<<NJOBS, 256, ATTN_SMEM>>>(pad);
    attn_merge_kernel<<<128, 256>>>(out);
}

// round 8
// speedup vs baseline: 3.1677x; 1.3784x over previous
#include <cuda_runtime.h>
#include <cuda_bf16.h>
#include <cstdint>

#define BSZ 4
#define SEQ 2048
#define EMB 1024
#define HD  64
#define MTOT (BSZ * SEQ)          // 8192 rows

// bf16 split operands
__device__ __nv_bfloat16 x_hi[MTOT * EMB];
__device__ __nv_bfloat16 x_lo[MTOT * EMB];
__device__ __nv_bfloat16 w_hi[192 * EMB];
__device__ __nv_bfloat16 w_lo[192 * EMB];
// projection outputs: Q,K transposed [dim][global row], V row-major
__device__ float g_qT[HD * MTOT];
__device__ float g_kT[HD * MTOT];
__device__ float g_vs[MTOT * HD];
// vmean
__device__ float g_vpart[BSZ * 8 * HD];
__device__ float g_vmean[BSZ * HD];
// attention split-key partials: 320 jobs (80 per batch)
#define NJOBS 320
__device__ float g_pm[NJOBS * 64];
__device__ float g_pl[NJOBS * 64];
__device__ float g_po[NJOBS * 64 * 64];

typedef unsigned long long u64;

__device__ __forceinline__ u64 splat2(float x) {
    u64 r; asm("mov.b64 %0, {%1, %1};" : "=l"(r) : "f"(x)); return r;
}
__device__ __forceinline__ u64 pack2(float lo, float hi) {
    u64 r; asm("mov.b64 %0, {%1, %2};" : "=l"(r) : "f"(lo), "f"(hi)); return r;
}
__device__ __forceinline__ void fma2(u64& d, u64 a, u64 b) {
    asm("fma.rn.f32x2 %0, %1, %2, %0;" : "+l"(d) : "l"(a), "l"(b));
}
__device__ __forceinline__ void mul2(u64& d, u64 s) {
    asm("mul.rn.f32x2 %0, %0, %1;" : "+l"(d) : "l"(s));
}
__device__ __forceinline__ void unpack2(u64 v, float& lo, float& hi) {
    asm("mov.b64 {%0, %1}, %2;" : "=f"(lo), "=f"(hi) : "l"(v));
}
__device__ __forceinline__ uint32_t smem_u32(const void* p) {
    uint32_t a;
    asm("{ .reg .u64 t; cvta.to.shared.u64 t, %1; cvt.u32.u64 %0, t; }"
        : "=r"(a) : "l"(p));
    return a;
}

// ---- portable tensor-core helpers (sm_80-class PTX, works on sm_103) ------
__device__ __forceinline__ void mma_bf16(float* d, const uint32_t* a,
                                         const uint32_t* b) {
    asm volatile(
        "mma.sync.aligned.m16n8k16.row.col.f32.bf16.bf16.f32 "
        "{%0,%1,%2,%3}, {%4,%5,%6,%7}, {%8,%9}, {%0,%1,%2,%3};"
        : "+f"(d[0]), "+f"(d[1]), "+f"(d[2]), "+f"(d[3])
        : "r"(a[0]), "r"(a[1]), "r"(a[2]), "r"(a[3]), "r"(b[0]), "r"(b[1]));
}
__device__ __forceinline__ void ldsm4(uint32_t* r, uint32_t addr) {
    asm volatile("ldmatrix.sync.aligned.m8n8.x4.shared.b16 {%0,%1,%2,%3}, [%4];"
                 : "=r"(r[0]), "=r"(r[1]), "=r"(r[2]), "=r"(r[3]) : "r"(addr));
}
__device__ __forceinline__ void cp16(uint32_t smaddr, const void* g) {
    asm volatile("cp.async.ca.shared.global [%0], [%1], 16;"
                 :: "r"(smaddr), "l"(g));
}
#define CP_COMMIT()  asm volatile("cp.async.commit_group;" ::: "memory")
#define CP_WAIT(n)   asm volatile("cp.async.wait_group %0;" :: "n"(n) : "memory")

// ---------------------------------------------------------------------------
// Kernel A: convert x -> hi/lo bf16
// ---------------------------------------------------------------------------
__global__ __launch_bounds__(256) void convert_x_kernel(const float* __restrict__ x)
{
    const int i = blockIdx.x * 256 + threadIdx.x;   // float4 index
    float4 v = reinterpret_cast<const float4*>(x)[i];
    __nv_bfloat16 h0 = __float2bfloat16_rn(v.x);
    __nv_bfloat16 h1 = __float2bfloat16_rn(v.y);
    __nv_bfloat16 h2 = __float2bfloat16_rn(v.z);
    __nv_bfloat16 h3 = __float2bfloat16_rn(v.w);
    __nv_bfloat16 l0 = __float2bfloat16_rn(v.x - __bfloat162float(h0));
    __nv_bfloat16 l1 = __float2bfloat16_rn(v.y - __bfloat162float(h1));
    __nv_bfloat16 l2 = __float2bfloat16_rn(v.z - __bfloat162float(h2));
    __nv_bfloat16 l3 = __float2bfloat16_rn(v.w - __bfloat162float(h3));
    uint2 oh, ol;
    oh.x = ((uint32_t)__bfloat16_as_ushort(h1) << 16) | __bfloat16_as_ushort(h0);
    oh.y = ((uint32_t)__bfloat16_as_ushort(h3) << 16) | __bfloat16_as_ushort(h2);
    ol.x = ((uint32_t)__bfloat16_as_ushort(l1) << 16) | __bfloat16_as_ushort(l0);
    ol.y = ((uint32_t)__bfloat16_as_ushort(l3) << 16) | __bfloat16_as_ushort(l2);
    reinterpret_cast<uint2*>(x_hi)[i] = oh;
    reinterpret_cast<uint2*>(x_lo)[i] = ol;
}

// ---------------------------------------------------------------------------
// Kernel B: convert stacked W (Wq|Wk|Wv) -> hi/lo bf16.
// ---------------------------------------------------------------------------
__global__ __launch_bounds__(256) void convert_w_kernel(
    const float* __restrict__ Wq, const float* __restrict__ Wk,
    const float* __restrict__ Wv)
{
    const int row = blockIdx.x;
    const float* src = (row < 64) ? (Wq + (size_t)row * EMB)
                     : (row < 128) ? (Wk + (size_t)(row - 64) * EMB)
                                   : (Wv + (size_t)(row - 128) * EMB);
    const int i = threadIdx.x;
    float4 v = reinterpret_cast<const float4*>(src)[i];
    __nv_bfloat16 h0 = __float2bfloat16_rn(v.x);
    __nv_bfloat16 h1 = __float2bfloat16_rn(v.y);
    __nv_bfloat16 h2 = __float2bfloat16_rn(v.z);
    __nv_bfloat16 h3 = __float2bfloat16_rn(v.w);
    __nv_bfloat16 l0 = __float2bfloat16_rn(v.x - __bfloat162float(h0));
    __nv_bfloat16 l1 = __float2bfloat16_rn(v.y - __bfloat162float(h1));
    __nv_bfloat16 l2 = __float2bfloat16_rn(v.z - __bfloat162float(h2));
    __nv_bfloat16 l3 = __float2bfloat16_rn(v.w - __bfloat162float(h3));
    uint2 oh, ol;
    oh.x = ((uint32_t)__bfloat16_as_ushort(h1) << 16) | __bfloat16_as_ushort(h0);
    oh.y = ((uint32_t)__bfloat16_as_ushort(h3) << 16) | __bfloat16_as_ushort(h2);
    ol.x = ((uint32_t)__bfloat16_as_ushort(l1) << 16) | __bfloat16_as_ushort(l0);
    ol.y = ((uint32_t)__bfloat16_as_ushort(l3) << 16) | __bfloat16_as_ushort(l2);
    reinterpret_cast<uint2*>(w_hi)[(size_t)row * (EMB / 4) + i] = oh;
    reinterpret_cast<uint2*>(w_lo)[(size_t)row * (EMB / 4) + i] = ol;
}

// ---------------------------------------------------------------------------
// Kernel C: QKV GEMM via mma.sync bf16 (3-term split).
// grid 128, 256 threads (8 warps = 2 M x 4 N). Tile M=64, N=192, K chunks 64.
// Double-buffered cp.async staging; ldmatrix operand loads, pitch 144B.
// ---------------------------------------------------------------------------
#define GPITCH 144                         // bytes per row (72 bf16)
#define OFF_AH 0
#define OFF_AL 9216
#define OFF_BH 18432
#define OFF_BL 46080
#define GBUF   73728
#define GEMM_SMEM (2 * GBUF)
#define CHUNKS 16

__device__ __forceinline__ void qkv_stage_cp(uint32_t bufb, int c, int row0, int tid)
{
#pragma unroll
    for (int u = 0; u < 2; u++) {
        int idx = tid + u * 256;           // 0..511
        int r = idx >> 3, seg = idx & 7;
        uint32_t dst = r * GPITCH + seg * 16;
        cp16(bufb + OFF_AH + dst, &x_hi[(size_t)(row0 + r) * EMB + c * 64 + seg * 8]);
        cp16(bufb + OFF_AL + dst, &x_lo[(size_t)(row0 + r) * EMB + c * 64 + seg * 8]);
    }
#pragma unroll
    for (int u = 0; u < 6; u++) {
        int idx = tid + u * 256;           // 0..1535
        int r = idx >> 3, seg = idx & 7;
        uint32_t dst = r * GPITCH + seg * 16;
        cp16(bufb + OFF_BH + dst, &w_hi[(size_t)r * EMB + c * 64 + seg * 8]);
        cp16(bufb + OFF_BL + dst, &w_lo[(size_t)r * EMB + c * 64 + seg * 8]);
    }
}

__global__ __launch_bounds__(256) void qkv_gemm_kernel()
{
    extern __shared__ char smg[];
    const uint32_t smb = smem_u32(smg);
    const int tid  = threadIdx.x;
    const int lane = tid & 31;
    const int w    = tid >> 5;
    const int wm   = w & 1;                // 0..1 -> m base 0/32
    const int wn   = w >> 1;               // 0..3 -> n base 0/48/96/144
    const int row0 = blockIdx.x * 64;

    float acc[2][6][4];
#pragma unroll
    for (int mm = 0; mm < 2; mm++)
#pragma unroll
        for (int nn = 0; nn < 6; nn++)
#pragma unroll
            for (int q = 0; q < 4; q++) acc[mm][nn][q] = 0.f;

    // ldmatrix address components (per-lane)
    const int g01 = (lane >> 3) & 1;        // groups 1,3
    const int g23 = (lane >> 4);            // groups 2,3
    const int tr  = lane & 7;

    qkv_stage_cp(smb, 0, row0, tid);
    CP_COMMIT();

    for (int c = 0; c < CHUNKS; c++) {
        const uint32_t bufb = smb + (c & 1) * GBUF;
        if (c < CHUNKS - 1) {
            qkv_stage_cp(smb + ((c + 1) & 1) * GBUF, c + 1, row0, tid);
            CP_COMMIT();
            CP_WAIT(1);
        } else {
            CP_WAIT(0);
        }
        __syncthreads();

#pragma unroll
        for (int pass = 0; pass < 3; pass++) {
            const uint32_t aoff = (pass == 2) ? OFF_AL : OFF_AH;
            const uint32_t boff = (pass == 1) ? OFF_BL : OFF_BH;
#pragma unroll
            for (int ks = 0; ks < 4; ks++) {
                uint32_t afr[2][4];
#pragma unroll
                for (int mm = 0; mm < 2; mm++) {
                    uint32_t addr = bufb + aoff
                        + (uint32_t)(wm * 32 + mm * 16 + g01 * 8 + tr) * GPITCH
                        + (uint32_t)(ks * 16 + g23 * 8) * 2;
                    ldsm4(afr[mm], addr);
                }
                uint32_t bfr[3][4];
#pragma unroll
                for (int ng = 0; ng < 3; ng++) {
                    uint32_t addr = bufb + boff
                        + (uint32_t)(wn * 48 + ng * 16 + g23 * 8 + tr) * GPITCH
                        + (uint32_t)(ks * 16 + g01 * 8) * 2;
                    ldsm4(bfr[ng], addr);
                }
#pragma unroll
                for (int mm = 0; mm < 2; mm++)
#pragma unroll
                    for (int nn = 0; nn < 6; nn++)
                        mma_bf16(acc[mm][nn], afr[mm], &bfr[nn >> 1][(nn & 1) * 2]);
            }
        }
        __syncthreads();
    }

    // epilogue
    const int mrow = lane >> 2;
    const int ncol = 2 * (lane & 3);
#pragma unroll
    for (int mm = 0; mm < 2; mm++) {
#pragma unroll
        for (int nn = 0; nn < 6; nn++) {
            const int n = wn * 48 + nn * 8 + ncol;
            const int m = row0 + wm * 32 + mm * 16 + mrow;
            const float* cvals = acc[mm][nn];
            if (n < 64) {
                g_qT[(size_t)n * MTOT + m]           = cvals[0];
                g_qT[(size_t)(n + 1) * MTOT + m]     = cvals[1];
                g_qT[(size_t)n * MTOT + m + 8]       = cvals[2];
                g_qT[(size_t)(n + 1) * MTOT + m + 8] = cvals[3];
            } else if (n < 128) {
                const int nk = n - 64;
                g_kT[(size_t)nk * MTOT + m]           = cvals[0];
                g_kT[(size_t)(nk + 1) * MTOT + m]     = cvals[1];
                g_kT[(size_t)nk * MTOT + m + 8]       = cvals[2];
                g_kT[(size_t)(nk + 1) * MTOT + m + 8] = cvals[3];
            } else {
                const int nv = n - 128;
                *reinterpret_cast<float2*>(&g_vs[(size_t)m * HD + nv]) =
                    make_float2(cvals[0], cvals[1]);
                *reinterpret_cast<float2*>(&g_vs[(size_t)(m + 8) * HD + nv]) =
                    make_float2(cvals[2], cvals[3]);
            }
        }
    }
}

// ---------------------------------------------------------------------------
// Kernel D: per-batch mean of V rows.
// ---------------------------------------------------------------------------
__global__ __launch_bounds__(256) void vmean1_kernel()
{
    const int b = blockIdx.x;
    const int c = blockIdx.y;
    const int d = threadIdx.x & 63;
    const int sub = threadIdx.x >> 6;
    float s = 0.f;
    const int i0 = c * 256 + sub * 64;
#pragma unroll 4
    for (int i = i0; i < i0 + 64; i++)
        s += g_vs[((size_t)b * SEQ + i) * HD + d];
    __shared__ float red[256];
    red[threadIdx.x] = s;
    __syncthreads();
    if (sub == 0)
        g_vpart[(b * 8 + c) * HD + d] =
            red[d] + red[64 + d] + red[128 + d] + red[192 + d];
}

__global__ __launch_bounds__(64) void vmean2_kernel()
{
    const int b = blockIdx.x;
    const int d = threadIdx.x;
    float s = 0.f;
#pragma unroll
    for (int c = 0; c < 8; c++) s += g_vpart[(b * 8 + c) * HD + d];
    g_vmean[b * HD + d] = s * (1.0f / SEQ);
}

// ---------------------------------------------------------------------------
// Kernel E: attention partials (FFMA2 path; staging from g_qT/g_kT).
// ---------------------------------------------------------------------------
#define PQ2 68
#define PK2 132
#define PV2 68
#define PP2 68

#define A_QT 0
#define A_KT (A_QT + 64 * PQ2)
#define A_V  (A_KT + 64 * PK2)
#define A_PT (A_V + 128 * PV2)
#define ATTN_SMEM ((A_PT + 128 * PP2) * 4)

__global__ __launch_bounds__(256) void attn_partial_kernel(
    const int* __restrict__ pad)
{
    const int bid = blockIdx.x;
    const int b = bid / 80;
    const int rem = bid - b * 80;
    int jq, ch;
    if (rem < 8)       { jq = rem;                   ch = 0; }
    else if (rem < 24) { jq = 8 + ((rem - 8) >> 1);  ch = (rem - 8) & 1; }
    else if (rem < 48) { jq = 16 + (rem - 24) / 3;   ch = (rem - 24) % 3; }
    else               { jq = 24 + ((rem - 48) >> 2); ch = (rem - 48) & 3; }
    const int q0 = jq * 64;
    const int kstart = ch * 512;
    const int kmax = q0 + 64;
    const int kend = (kstart + 512 < kmax) ? kstart + 512 : kmax;
    const int nkt = (kend - kstart + 127) >> 7;

    const int tid  = threadIdx.x;
    const int lane = tid & 31;
    const int ty8  = (tid >> 5) * 8;

    extern __shared__ float smem[];
    float* sQt = smem + A_QT;
    float* sKt = smem + A_KT;
    float* sV  = smem + A_V;
    float* sPt = smem + A_PT;
    __shared__ int sPad[128];

#pragma unroll
    for (int u = 0; u < 4; u++) {
        int idx = tid + u * 256;
        int d = idx >> 4, f = (idx & 15) * 4;
        float4 v4 = *reinterpret_cast<const float4*>(
            &g_qT[(size_t)d * MTOT + b * SEQ + q0 + f]);
        *reinterpret_cast<float4*>(&sQt[d * PQ2 + f]) = v4;
    }

    float m[8], l[8];
    u64 o2[4][2];
#pragma unroll
    for (int r = 0; r < 8; r++) { m[r] = -3.0e38f; l[r] = 0.f; }
#pragma unroll
    for (int p = 0; p < 4; p++) { o2[p][0] = 0ULL; o2[p][1] = 0ULL; }

    for (int kt = 0; kt < nkt; kt++) {
        const int k0 = kstart + kt * 128;
        __syncthreads();

#pragma unroll
        for (int u = 0; u < 8; u++) {
            int idx = tid + u * 256;
            int d = idx >> 5, f = (idx & 31) * 4;
            float4 v4 = *reinterpret_cast<const float4*>(
                &g_kT[(size_t)d * MTOT + b * SEQ + k0 + f]);
            *reinterpret_cast<float4*>(&sKt[d * PK2 + f]) = v4;
        }
#pragma unroll
        for (int u = 0; u < 8; u++) {
            int idx = tid + u * 256;
            int r = idx >> 4, f = (idx & 15) * 4;
            float4 a = *reinterpret_cast<const float4*>(
                &g_vs[((size_t)b * SEQ + k0 + r) * HD + f]);
            *reinterpret_cast<float4*>(&sV[r * PV2 + f]) = a;
        }
        if (tid < 128) sPad[tid] = pad[b * SEQ + k0 + tid];
        __syncthreads();

        u64 s2[4][4];
#pragma unroll
        for (int p = 0; p < 4; p++)
#pragma unroll
            for (int i = 0; i < 4; i++) s2[p][i] = 0ULL;
#pragma unroll 8
        for (int d = 0; d < 64; d++) {
            ulonglong2 qA = *reinterpret_cast<const ulonglong2*>(&sQt[d * PQ2 + ty8]);
            ulonglong2 qB = *reinterpret_cast<const ulonglong2*>(&sQt[d * PQ2 + ty8 + 4]);
            float4 kv = *reinterpret_cast<const float4*>(&sKt[d * PK2 + lane * 4]);
            u64 k0s = splat2(kv.x), k1s = splat2(kv.y);
            u64 k2s = splat2(kv.z), k3s = splat2(kv.w);
            fma2(s2[0][0], qA.x, k0s); fma2(s2[0][1], qA.x, k1s);
            fma2(s2[0][2], qA.x, k2s); fma2(s2[0][3], qA.x, k3s);
            fma2(s2[1][0], qA.y, k0s); fma2(s2[1][1], qA.y, k1s);
            fma2(s2[1][2], qA.y, k2s); fma2(s2[1][3], qA.y, k3s);
            fma2(s2[2][0], qB.x, k0s); fma2(s2[2][1], qB.x, k1s);
            fma2(s2[2][2], qB.x, k2s); fma2(s2[2][3], qB.x, k3s);
            fma2(s2[3][0], qB.y, k0s); fma2(s2[3][1], qB.y, k1s);
            fma2(s2[3][2], qB.y, k2s); fma2(s2[3][3], qB.y, k3s);
        }

        float sv[8][4];
#pragma unroll
        for (int p = 0; p < 4; p++)
#pragma unroll
            for (int i = 0; i < 4; i++)
                unpack2(s2[p][i], sv[2 * p][i], sv[2 * p + 1][i]);

        float p8[8][4], scl[8];
#pragma unroll
        for (int r = 0; r < 8; r++) {
            const int qi = q0 + ty8 + r;
#pragma unroll
            for (int i = 0; i < 4; i++) {
                const int kj = k0 + lane * 4 + i;
                const bool masked = (kj > qi) || (sPad[lane * 4 + i] == 0);
                sv[r][i] = (masked ? -1e9f : sv[r][i]) * 0.125f;
            }
            float tm = fmaxf(fmaxf(sv[r][0], sv[r][1]), fmaxf(sv[r][2], sv[r][3]));
            tm = fmaxf(tm, __shfl_xor_sync(0xffffffffu, tm, 1));
            tm = fmaxf(tm, __shfl_xor_sync(0xffffffffu, tm, 2));
            tm = fmaxf(tm, __shfl_xor_sync(0xffffffffu, tm, 4));
            tm = fmaxf(tm, __shfl_xor_sync(0xffffffffu, tm, 8));
            tm = fmaxf(tm, __shfl_xor_sync(0xffffffffu, tm, 16));
            const float mnew = fmaxf(m[r], tm);
            scl[r] = __expf(m[r] - mnew);
            float tl = 0.f;
#pragma unroll
            for (int i = 0; i < 4; i++) { p8[r][i] = __expf(sv[r][i] - mnew); tl += p8[r][i]; }
            tl += __shfl_xor_sync(0xffffffffu, tl, 1);
            tl += __shfl_xor_sync(0xffffffffu, tl, 2);
            tl += __shfl_xor_sync(0xffffffffu, tl, 4);
            tl += __shfl_xor_sync(0xffffffffu, tl, 8);
            tl += __shfl_xor_sync(0xffffffffu, tl, 16);
            l[r] = l[r] * scl[r] + tl;
            m[r] = mnew;
        }
#pragma unroll
        for (int p = 0; p < 4; p++) {
            u64 sp = pack2(scl[2 * p], scl[2 * p + 1]);
            mul2(o2[p][0], sp);
            mul2(o2[p][1], sp);
        }
#pragma unroll
        for (int i = 0; i < 4; i++) {
            const int key = lane * 4 + i;
            *reinterpret_cast<float4*>(&sPt[key * PP2 + ty8]) =
                make_float4(p8[0][i], p8[1][i], p8[2][i], p8[3][i]);
            *reinterpret_cast<float4*>(&sPt[key * PP2 + ty8 + 4]) =
                make_float4(p8[4][i], p8[5][i], p8[6][i], p8[7][i]);
        }
        __syncthreads();

#pragma unroll 8
        for (int j = 0; j < 128; j++) {
            ulonglong2 pA = *reinterpret_cast<const ulonglong2*>(&sPt[j * PP2 + ty8]);
            ulonglong2 pB = *reinterpret_cast<const ulonglong2*>(&sPt[j * PP2 + ty8 + 4]);
            float2 v2 = *reinterpret_cast<const float2*>(&sV[j * PV2 + lane * 2]);
            u64 v0 = splat2(v2.x), v1 = splat2(v2.y);
            fma2(o2[0][0], pA.x, v0); fma2(o2[0][1], pA.x, v1);
            fma2(o2[1][0], pA.y, v0); fma2(o2[1][1], pA.y, v1);
            fma2(o2[2][0], pB.x, v0); fma2(o2[2][1], pB.x, v1);
            fma2(o2[3][0], pB.y, v0); fma2(o2[3][1], pB.y, v1);
        }
    }

    if (lane == 0) {
#pragma unroll
        for (int r = 0; r < 8; r++) {
            g_pm[bid * 64 + ty8 + r] = m[r];
            g_pl[bid * 64 + ty8 + r] = l[r];
        }
    }
#pragma unroll
    for (int p = 0; p < 4; p++) {
        float aLo, aHi, bLo, bHi;
        unpack2(o2[p][0], aLo, aHi);
        unpack2(o2[p][1], bLo, bHi);
        *reinterpret_cast<float2*>(
            &g_po[(size_t)bid * 4096 + (ty8 + 2 * p) * 64 + lane * 2]) =
            make_float2(aLo, bLo);
        *reinterpret_cast<float2*>(
            &g_po[(size_t)bid * 4096 + (ty8 + 2 * p + 1) * 64 + lane * 2]) =
            make_float2(aHi, bHi);
    }
}

// ---------------------------------------------------------------------------
// Kernel F: merge partials.
// ---------------------------------------------------------------------------
__global__ __launch_bounds__(256) void attn_merge_kernel(float* __restrict__ out)
{
    const int b  = blockIdx.x >> 5;
    const int jq = blockIdx.x & 31;
    int off;
    if (jq < 8)       off = jq;
    else if (jq < 16) off = 8 + 2 * (jq - 8);
    else if (jq < 24) off = 24 + 3 * (jq - 16);
    else              off = 48 + 4 * (jq - 24);
    const int nch = (jq >> 3) + 1;
    const int jbase = b * 80 + off;
    const int q0 = jq * 64;

    const int d  = threadIdx.x & 63;
    const int r0 = threadIdx.x >> 6;

    for (int rr = 0; rr < 16; rr++) {
        const int row = r0 + rr * 4;
        float M = -3.0e38f;
        float mi[5], li[5];
#pragma unroll 5
        for (int i = 0; i < 5; i++) {
            if (i < nch) {
                mi[i] = g_pm[(jbase + i) * 64 + row];
                li[i] = g_pl[(jbase + i) * 64 + row];
                M = fmaxf(M, mi[i]);
            }
        }
        float L = 0.f, O = 0.f;
#pragma unroll 5
        for (int i = 0; i < 5; i++) {
            if (i < nch) {
                float w = __expf(mi[i] - M);
                L += li[i] * w;
                O += g_po[(size_t)(jbase + i) * 4096 + row * 64 + d] * w;
            }
        }
        float res = (M <= -1.0e8f) ? g_vmean[b * HD + d] : O / L;
        out[((size_t)b * SEQ + q0 + row) * HD + d] = res;
    }
}

// ---------------------------------------------------------------------------
extern "C" void kernel_launch(void* const* d_in, const int* in_sizes, int n_in,
                              void* d_out, int out_size)
{
    const float* x   = (const float*)d_in[0];
    const int*   pad = (const int*)  d_in[1];
    const float* Wq  = (const float*)d_in[2];
    const float* Wk  = (const float*)d_in[3];
    const float* Wv  = (const float*)d_in[4];
    float* out = (float*)d_out;

    cudaFuncSetAttribute(qkv_gemm_kernel,
                         cudaFuncAttributeMaxDynamicSharedMemorySize, GEMM_SMEM);
    cudaFuncSetAttribute(attn_partial_kernel,
                         cudaFuncAttributeMaxDynamicSharedMemorySize, ATTN_SMEM);

    convert_x_kernel<<<(MTOT * EMB / 4) / 256, 256>>>(x);
    convert_w_kernel<<<192, 256>>>(Wq, Wk, Wv);
    qkv_gemm_kernel<<<128, 256, GEMM_SMEM>>>();
    vmean1_kernel<<<dim3(BSZ, 8), 256>>>();
    vmean2_kernel<<<BSZ, 64>>>();
    attn_partial_kernel<<<NJOBS, 256, ATTN_SMEM>>>(pad);
    attn_merge_kernel<<<128, 256>>>(out);
}